// round 4
// baseline (speedup 1.0000x reference)
#include <cuda_runtime.h>

#define NN 8192
#define FIN 512
#define FF 256
#define ALPHA 0.2f

// Scratch (allocation-free rule: __device__ globals)
__device__ float g_h[NN * FF];     // 8 MB
__device__ float g_s1[NN];
__device__ float g_s2[NN];

// ---------------------------------------------------------------------------
// Kernel 1: h = X @ W   (8192x512 @ 512x256)
// Block = 256 threads computes 32 rows x 256 cols (full width).
// K staged in 32-wide tiles in smem (layout Xs[k][r], stride 36 for float4
// broadcast reads).
// ---------------------------------------------------------------------------
__global__ __launch_bounds__(256) void gemm_xw(const float* __restrict__ X,
                                               const float* __restrict__ W) {
    __shared__ float Xs[32 * 36];
    const int t = threadIdx.x;
    const int i0 = blockIdx.x * 32;
    const int c = t;  // output column

    float acc[32];
#pragma unroll
    for (int r = 0; r < 32; r++) acc[r] = 0.f;

    const int kk = t & 31;
    const int rb = t >> 5;

    for (int k0 = 0; k0 < FIN; k0 += 32) {
#pragma unroll
        for (int q = 0; q < 4; q++) {
            int r = rb + 8 * q;
            Xs[kk * 36 + r] = X[(i0 + r) * FIN + k0 + kk];
        }
        __syncthreads();
#pragma unroll
        for (int k = 0; k < 32; k++) {
            float wv = W[(k0 + k) * FF + c];
            const float4* xp = reinterpret_cast<const float4*>(&Xs[k * 36]);
#pragma unroll
            for (int u = 0; u < 8; u++) {
                float4 xv = xp[u];
                acc[4 * u + 0] = fmaf(xv.x, wv, acc[4 * u + 0]);
                acc[4 * u + 1] = fmaf(xv.y, wv, acc[4 * u + 1]);
                acc[4 * u + 2] = fmaf(xv.z, wv, acc[4 * u + 2]);
                acc[4 * u + 3] = fmaf(xv.w, wv, acc[4 * u + 3]);
            }
        }
        __syncthreads();
    }
#pragma unroll
    for (int r = 0; r < 32; r++) g_h[(i0 + r) * FF + c] = acc[r];
}

// ---------------------------------------------------------------------------
// Kernel 2: s1[i] = h[i,:] . a[0:256],  s2[i] = h[i,:] . a[256:512]
// One warp per row.
// ---------------------------------------------------------------------------
__global__ __launch_bounds__(256) void svec_kernel(const float* __restrict__ a) {
    __shared__ float as[2 * FF];
    const int t = threadIdx.x;
    as[t] = a[t];
    as[t + 256] = a[t + 256];
    __syncthreads();

    const int warp = t >> 5;
    const int lane = t & 31;
    const int row = blockIdx.x * 8 + warp;

    float s1 = 0.f, s2 = 0.f;
#pragma unroll
    for (int q = 0; q < 8; q++) {
        int f = lane + 32 * q;
        float v = g_h[row * FF + f];
        s1 = fmaf(v, as[f], s1);
        s2 = fmaf(v, as[FF + f], s2);
    }
#pragma unroll
    for (int off = 16; off; off >>= 1) {
        s1 += __shfl_xor_sync(0xFFFFFFFFu, s1, off);
        s2 += __shfl_xor_sync(0xFFFFFFFFu, s2, off);
    }
    if (lane == 0) {
        g_s1[row] = s1;
        g_s2[row] = s2;
    }
}

// ---------------------------------------------------------------------------
// Kernel 3: fused masked-softmax attention + P@h + ELU.
// Block = 256 threads handles 32 output rows x 256 features.
// Phase 0: per-row max over neighbors (lrelu is monotone, so
//          max_j masked e_ij = lrelu(s1_i + max_{adj} s2_j); we compute the
//          max of the full e directly for robustness).
// Then loop over 32-wide j chunks:
//   A : P tile (32x32) -> smem, running Z per row in registers
//   A2: stage h chunk (32x256) -> smem
//   B : micro-GEMM: thread owns 8 rows x 4 features (float4)
// Epilogue: scale by 1/Z, ELU, float4 store.
// ---------------------------------------------------------------------------
__global__ __launch_bounds__(256) void gat_main(const int* __restrict__ adj,
                                                float* __restrict__ out) {
    __shared__ float hs[32 * FF];   // 32 KB
    __shared__ float ps[32 * 33];   // P tile, padded stride
    __shared__ float s1s[32];
    __shared__ float ms[32];
    __shared__ float zs[32];

    const int t = threadIdx.x;
    const int i0 = blockIdx.x * 32;
    const int warp = t >> 5;
    const int lane = t & 31;

    if (t < 32) s1s[t] = g_s1[i0 + t];

    // ---- Phase 0: row max over allowed j (each warp handles 4 rows) ----
#pragma unroll
    for (int u = 0; u < 4; u++) {
        const int r = warp * 4 + u;
        const int* arow = adj + (i0 + r) * NN;
        float m = -3.0e38f;
#pragma unroll 4
        for (int jj = lane; jj < NN; jj += 32) {
            int av = arow[jj];
            if (av > 0) m = fmaxf(m, g_s2[jj]);
        }
#pragma unroll
        for (int off = 16; off; off >>= 1)
            m = fmaxf(m, __shfl_xor_sync(0xFFFFFFFFu, m, off));
        if (lane == 0) {
            // convert s2-max to e-max via monotone lrelu; sentinel if no nbrs
            if (m < -1.0e37f) {
                ms[r] = -3.0e38f;
            } else {
                float e = s1s[r] + m;
                ms[r] = fmaxf(e, ALPHA * e);
            }
        }
    }
    __syncthreads();

    float4 acc[8];
#pragma unroll
    for (int u = 0; u < 8; u++) acc[u] = make_float4(0.f, 0.f, 0.f, 0.f);
    float zpart[4] = {0.f, 0.f, 0.f, 0.f};

    const int jlane = t & 31;   // phase-A role: j within chunk
    const int rg = t >> 5;      // phase-A role: row group (4 rows)
    const int fg = t & 63;      // phase-B role: feature group (4 feats)
    const int rg2 = t >> 6;     // phase-B role: row group (8 rows)

    for (int jc = 0; jc < NN; jc += 32) {
        const int jg = jc + jlane;
        const float s2j = g_s2[jg];

        // ---- Phase A: P tile + running Z ----
#pragma unroll
        for (int u = 0; u < 4; u++) {
            const int r = rg * 4 + u;
            const float m = ms[r];
            const int av = adj[(i0 + r) * NN + jg];
            float e = s1s[r] + s2j;
            e = fmaxf(e, ALPHA * e);
            float p;
            if (m < -1.0e37f) {
                p = 1.0f;  // degenerate row: uniform softmax over all j
            } else {
                p = (av > 0) ? __expf(e - m) : 0.0f;
            }
            ps[r * 33 + jlane] = p;
            zpart[u] += p;
        }

        // ---- Phase A2: stage h[jc..jc+31][:] into smem ----
#pragma unroll
        for (int it = 0; it < 8; it++) {
            int idx = t + 256 * it;
            int row = idx >> 6;
            int c4 = (idx & 63) << 2;
            *reinterpret_cast<float4*>(&hs[row * FF + c4]) =
                *reinterpret_cast<const float4*>(&g_h[(jc + row) * FF + c4]);
        }
        __syncthreads();

        // ---- Phase B: acc += P_tile @ h_tile ----
#pragma unroll 8
        for (int j = 0; j < 32; j++) {
            float4 hv = *reinterpret_cast<const float4*>(&hs[j * FF + fg * 4]);
#pragma unroll
            for (int u = 0; u < 8; u++) {
                float p = ps[(rg2 * 8 + u) * 33 + j];
                acc[u].x = fmaf(p, hv.x, acc[u].x);
                acc[u].y = fmaf(p, hv.y, acc[u].y);
                acc[u].z = fmaf(p, hv.z, acc[u].z);
                acc[u].w = fmaf(p, hv.w, acc[u].w);
            }
        }
        __syncthreads();
    }

    // ---- Reduce Z across the 32 j-lanes of each warp ----
#pragma unroll
    for (int u = 0; u < 4; u++) {
        float z = zpart[u];
#pragma unroll
        for (int off = 16; off; off >>= 1)
            z += __shfl_xor_sync(0xFFFFFFFFu, z, off);
        if (lane == 0) zs[rg * 4 + u] = z;
    }
    __syncthreads();

    // ---- Epilogue: 1/Z, ELU, store ----
#pragma unroll
    for (int u = 0; u < 8; u++) {
        const int r = rg2 * 8 + u;
        const float inv = 1.0f / zs[r];
        float4 v;
        v.x = acc[u].x * inv;
        v.y = acc[u].y * inv;
        v.z = acc[u].z * inv;
        v.w = acc[u].w * inv;
        v.x = (v.x > 0.f) ? v.x : (__expf(v.x) - 1.0f);
        v.y = (v.y > 0.f) ? v.y : (__expf(v.y) - 1.0f);
        v.z = (v.z > 0.f) ? v.z : (__expf(v.z) - 1.0f);
        v.w = (v.w > 0.f) ? v.w : (__expf(v.w) - 1.0f);
        *reinterpret_cast<float4*>(&out[(i0 + r) * FF + fg * 4]) = v;
    }
}

// ---------------------------------------------------------------------------
extern "C" void kernel_launch(void* const* d_in, const int* in_sizes, int n_in,
                              void* d_out, int out_size) {
    const float* X = (const float*)d_in[0];     // [8192, 512]
    const int* adj = (const int*)d_in[1];       // [8192, 8192]
    const float* W = (const float*)d_in[2];     // [512, 256]
    const float* a = (const float*)d_in[3];     // [512, 1]
    float* out = (float*)d_out;                 // [8192, 256]

    gemm_xw<<<NN / 32, 256>>>(X, W);
    svec_kernel<<<NN / 8, 256>>>(a);
    gat_main<<<NN / 32, 256>>>(adj, out);
}

// round 7
// speedup vs baseline: 3.9340x; 3.9340x over previous
#include <cuda_runtime.h>
#include <cuda_fp16.h>
#include <cstdint>

#define NN 8192
#define FIN 512
#define FF 256
#define MB 64          // rows per CTA in gat kernel
#define KC 64          // K chunk

// ---------------- device scratch (allocation-free rule) ----------------
__device__ float  g_h[NN * FF];                  // fp32 h row-major
__device__ __half g_hT_hi[(size_t)FF * NN];      // fp16 hi, feature-major
__device__ __half g_hT_lo[(size_t)FF * NN];      // fp16 lo residual
__device__ float  g_s1[NN], g_s2[NN];
__device__ uint32_t g_a2[NN], g_c2[NN];          // A_i,A_i / C_i,C_i packed half2
__device__ uint4  g_bd4[NN / 4];                 // (Bpair, Dpair) interleaved
__device__ __half g_adjh[(size_t)NN * NN];       // adj as fp16 {0,1}

// ---------------- helpers ----------------
__device__ __forceinline__ uint32_t smem_u32(const void* p) {
    uint32_t a;
    asm("{ .reg .u64 t; cvta.to.shared.u64 t, %1; cvt.u32.u64 %0, t; }" : "=r"(a) : "l"(p));
    return a;
}
__device__ __forceinline__ __half2 u2h2(uint32_t u) {
    __half2 h; *reinterpret_cast<uint32_t*>(&h) = u; return h;
}
__device__ __forceinline__ uint32_t h22u(__half2 h) {
    return *reinterpret_cast<uint32_t*>(&h);
}
#define CP16(dst, src) \
    asm volatile("cp.async.cg.shared.global [%0], [%1], 16;" :: "r"(dst), "l"(src) : "memory")
#define LDSM4(r, addr) \
    asm volatile("ldmatrix.sync.aligned.m8n8.x4.shared.b16 {%0,%1,%2,%3}, [%4];" \
        : "=r"((r)[0]), "=r"((r)[1]), "=r"((r)[2]), "=r"((r)[3]) : "r"(addr))
#define MMA16816(d, a, b0, b1) \
    asm volatile("mma.sync.aligned.m16n8k16.row.col.f32.f16.f16.f32 " \
        "{%0,%1,%2,%3},{%4,%5,%6,%7},{%8,%9},{%0,%1,%2,%3};" \
        : "+f"((d)[0]), "+f"((d)[1]), "+f"((d)[2]), "+f"((d)[3]) \
        : "r"((a)[0]), "r"((a)[1]), "r"((a)[2]), "r"((a)[3]), "r"(b0), "r"(b1))

// ---------------- SMEM layout for gat_hmma ----------------
#define SM_BD 0                      // 32768 B : BD tables
#define SM_P 32768                   // 9216 B  : P tile 64 x (64 fp16, pitch 144B)
#define SM_B0 41984                  // 2 x 73728 B : B tiles 512 rows x 144B
#define SM_ZS 189440                 // 256 B   : z per row
#define GAT_SMEM 189696

// ---------------------------------------------------------------------------
// adj (int 0/1) -> fp16 {0,1}
// ---------------------------------------------------------------------------
__global__ __launch_bounds__(256) void adjconv(const int* __restrict__ adj) {
    size_t base = ((size_t)blockIdx.x * 256 + threadIdx.x) * 8;
    const int4* s = reinterpret_cast<const int4*>(adj + base);
    int4 a = s[0], b = s[1];
    uint4 o;
    o.x = (uint32_t)a.x * 0x3C00u + (uint32_t)a.y * 0x3C000000u;
    o.y = (uint32_t)a.z * 0x3C00u + (uint32_t)a.w * 0x3C000000u;
    o.z = (uint32_t)b.x * 0x3C00u + (uint32_t)b.y * 0x3C000000u;
    o.w = (uint32_t)b.z * 0x3C00u + (uint32_t)b.w * 0x3C000000u;
    *reinterpret_cast<uint4*>(g_adjh + base) = o;
}

// ---------------------------------------------------------------------------
// h = X @ W ; also emit transposed fp16 hi/lo split of h.
// ---------------------------------------------------------------------------
__global__ __launch_bounds__(256) void gemm_xw(const float* __restrict__ X,
                                               const float* __restrict__ W) {
    __shared__ float Xs[32 * 36];
    __shared__ float T[256 * 33];
    const int t = threadIdx.x;
    const int i0 = blockIdx.x * 32;
    const int c = t;

    float acc[32];
#pragma unroll
    for (int r = 0; r < 32; r++) acc[r] = 0.f;
    const int kk = t & 31;
    const int rb = t >> 5;

    for (int k0 = 0; k0 < FIN; k0 += 32) {
#pragma unroll
        for (int q = 0; q < 4; q++) {
            int r = rb + 8 * q;
            Xs[kk * 36 + r] = X[(i0 + r) * FIN + k0 + kk];
        }
        __syncthreads();
#pragma unroll
        for (int k = 0; k < 32; k++) {
            float wv = W[(k0 + k) * FF + c];
            const float4* xp = reinterpret_cast<const float4*>(&Xs[k * 36]);
#pragma unroll
            for (int u = 0; u < 8; u++) {
                float4 xv = xp[u];
                acc[4 * u + 0] = fmaf(xv.x, wv, acc[4 * u + 0]);
                acc[4 * u + 1] = fmaf(xv.y, wv, acc[4 * u + 1]);
                acc[4 * u + 2] = fmaf(xv.z, wv, acc[4 * u + 2]);
                acc[4 * u + 3] = fmaf(xv.w, wv, acc[4 * u + 3]);
            }
        }
        __syncthreads();
    }
#pragma unroll
    for (int r = 0; r < 32; r++) {
        g_h[(i0 + r) * FF + c] = acc[r];
        T[c * 33 + r] = acc[r];
    }
    __syncthreads();
    const int warp = t >> 5, lane = t & 31;
#pragma unroll 4
    for (int ff = 0; ff < 32; ff++) {
        const int f = warp * 32 + ff;
        float v = T[f * 33 + lane];
        __half hv = __float2half_rn(v);
        __half lv = __float2half_rn(v - __half2float(hv));
        g_hT_hi[(size_t)f * NN + i0 + lane] = hv;
        g_hT_lo[(size_t)f * NN + i0 + lane] = lv;
    }
}

// ---------------------------------------------------------------------------
// s1, s2 dot products
// ---------------------------------------------------------------------------
__global__ __launch_bounds__(256) void svec_kernel(const float* __restrict__ a) {
    __shared__ float as[2 * FF];
    const int t = threadIdx.x;
    as[t] = a[t];
    as[t + 256] = a[t + 256];
    __syncthreads();
    const int warp = t >> 5, lane = t & 31;
    const int row = blockIdx.x * 8 + warp;
    float s1 = 0.f, s2 = 0.f;
#pragma unroll
    for (int q = 0; q < 8; q++) {
        int f = lane + 32 * q;
        float v = g_h[row * FF + f];
        s1 = fmaf(v, as[f], s1);
        s2 = fmaf(v, as[FF + f], s2);
    }
#pragma unroll
    for (int o = 16; o; o >>= 1) {
        s1 += __shfl_xor_sync(0xFFFFFFFFu, s1, o);
        s2 += __shfl_xor_sync(0xFFFFFFFFu, s2, o);
    }
    if (lane == 0) { g_s1[row] = s1; g_s2[row] = s2; }
}

// ---------------------------------------------------------------------------
// Tables: mx = max s2; A_i, C_i (per row), B_j, D_j (per col), fp16 packed.
// p_ij = adj * max(A_i*B_j, C_i*D_j) = adj * exp(lrelu(s1_i+s2_j) - m_i)
// ---------------------------------------------------------------------------
__global__ __launch_bounds__(256) void rowm_kernel() {
    __shared__ float red[256];
    const int t = threadIdx.x;
    float m = -3.0e38f;
    for (int i = t; i < NN; i += 256) m = fmaxf(m, g_s2[i]);
    red[t] = m;
    __syncthreads();
    for (int s = 128; s; s >>= 1) {
        if (t < s) red[t] = fmaxf(red[t], red[t + s]);
        __syncthreads();
    }
    const float mx = red[0];
    for (int i = t; i < NN; i += 256) {
        float u = g_s1[i] + mx;
        float mm = fmaxf(u, 0.2f * u);
        __half A = __float2half_rn(expf(u - mm));
        __half C = __float2half_rn(expf(0.2f * u - mm));
        g_a2[i] = h22u(__halves2half2(A, A));
        g_c2[i] = h22u(__halves2half2(C, C));
    }
    uint2* bd = reinterpret_cast<uint2*>(g_bd4);
    for (int j2 = t; j2 < NN / 2; j2 += 256) {
        float v0 = g_s2[2 * j2] - mx, v1 = g_s2[2 * j2 + 1] - mx;
        __half B0 = __float2half_rn(expf(v0)), B1 = __float2half_rn(expf(v1));
        __half D0 = __float2half_rn(expf(0.2f * v0)), D1 = __float2half_rn(expf(0.2f * v1));
        bd[j2] = make_uint2(h22u(__halves2half2(B0, B1)), h22u(__halves2half2(D0, D1)));
    }
}

// ---------------------------------------------------------------------------
// Fused GAT on HMMA. 128 CTAs x (M=64, N=256), K=8192 in 64-chunks.
// All 8 warps: produce P tile (packed fp16, exp-free) then mma.sync.
// Warp grid M2 x N4, warp tile 32x64. Z via ones-column MMA (n==0 warps).
// ---------------------------------------------------------------------------
__global__ __launch_bounds__(256, 1) void gat_hmma(float* __restrict__ out) {
    extern __shared__ char smem[];
    const uint32_t sb = smem_u32(smem);
    const int t = threadIdx.x;
    const int lane = t & 31, wid = t >> 5;
    const int midx = wid >> 2, nidx = wid & 3;
    const int i0 = blockIdx.x * MB;

    // preload BD tables (32 KB)
    {
        const uint4* src = g_bd4;
        uint4* dst = reinterpret_cast<uint4*>(smem + SM_BD);
#pragma unroll
        for (int q = 0; q < 8; q++) dst[t + 256 * q] = src[t + 256 * q];
    }

    // P-gen role: row pr_ (0..63), segment seg (16 j's each)
    const int pr_ = t >> 2;
    const int seg = t & 3;
    const __half2 A2 = u2h2(g_a2[i0 + pr_]);
    const __half2 C2 = u2h2(g_c2[i0 + pr_]);
    const __half* adjrow = g_adjh + (size_t)(i0 + pr_) * NN + seg * 16;

    // first B tile copy (chunk 0 -> buf 0)
    {
        const __half* sH = g_hT_hi + (size_t)t * NN;
        const __half* sL = g_hT_lo + (size_t)t * NN;
        uint32_t dH = sb + SM_B0 + (uint32_t)t * 144;
        uint32_t dL = dH + 256 * 144;
#pragma unroll
        for (int i = 0; i < 8; i++) { CP16(dH + i * 16, sH + i * 8); CP16(dL + i * 16, sL + i * 8); }
        asm volatile("cp.async.commit_group;" ::: "memory");
    }
    uint4 u0 = reinterpret_cast<const uint4*>(adjrow)[0];
    uint4 u1 = reinterpret_cast<const uint4*>(adjrow)[1];
    __syncthreads();  // BD ready

    float acc[2][8][4];
#pragma unroll
    for (int a = 0; a < 2; a++)
#pragma unroll
        for (int b = 0; b < 8; b++)
#pragma unroll
            for (int c = 0; c < 4; c++) acc[a][b][c] = 0.f;
    float zac[2][4] = {{0.f, 0.f, 0.f, 0.f}, {0.f, 0.f, 0.f, 0.f}};
    const uint32_t ONES = 0x3C003C00u;

    // ldmatrix lane geometry
    const uint32_t arow = (uint32_t)(midx * 32 + ((lane >> 3) & 1) * 8 + (lane & 7));
    const uint32_t acolb = (uint32_t)((lane >> 4) * 16);
    const uint32_t brow0 = (uint32_t)(nidx * 64 + (lane >> 4) * 8 + (lane & 7));
    const uint32_t bcolb = (uint32_t)(((lane >> 3) & 1) * 16);

#pragma unroll 1
    for (int c = 0; c < 128; c++) {
        const int buf = c & 1;
        const int jc = c * KC;
        if (c < 127) {  // stage B chunk c+1 into other buffer
            const __half* sH = g_hT_hi + (size_t)t * NN + jc + KC;
            const __half* sL = g_hT_lo + (size_t)t * NN + jc + KC;
            uint32_t dH = sb + SM_B0 + (uint32_t)(buf ^ 1) * 73728 + (uint32_t)t * 144;
            uint32_t dL = dH + 256 * 144;
#pragma unroll
            for (int i = 0; i < 8; i++) { CP16(dH + i * 16, sH + i * 8); CP16(dL + i * 16, sL + i * 8); }
            asm volatile("cp.async.commit_group;" ::: "memory");
        }
        // ---- P tile: 16 elements per thread, exp-free ----
        {
            const uint4* bd4s = reinterpret_cast<const uint4*>(smem + SM_BD) + (jc >> 2) + seg * 4;
            uint32_t pst = sb + SM_P + (uint32_t)pr_ * 144 + (uint32_t)seg * 32;
            uint32_t am[8] = {u0.x, u0.y, u0.z, u0.w, u1.x, u1.y, u1.z, u1.w};
#pragma unroll
            for (int q = 0; q < 4; q++) {
                uint4 bd = bd4s[q];
                __half2 m0 = __hmax2(__hmul2(A2, u2h2(bd.x)), __hmul2(C2, u2h2(bd.y)));
                __half2 m1 = __hmax2(__hmul2(A2, u2h2(bd.z)), __hmul2(C2, u2h2(bd.w)));
                uint32_t p0 = h22u(__hmul2(m0, u2h2(am[2 * q])));
                uint32_t p1 = h22u(__hmul2(m1, u2h2(am[2 * q + 1])));
                asm volatile("st.shared.v2.b32 [%0], {%1,%2};" :: "r"(pst + q * 8), "r"(p0), "r"(p1) : "memory");
            }
        }
        if (c < 127) { asm volatile("cp.async.wait_group 1;" ::: "memory"); }
        else         { asm volatile("cp.async.wait_group 0;" ::: "memory"); }
        __syncthreads();
        // prefetch adj for next chunk (latency hidden under MMA)
        if (c < 127) {
            const uint4* na = reinterpret_cast<const uint4*>(adjrow + jc + KC);
            u0 = na[0]; u1 = na[1];
        }
        // ---- MMA phase ----
        const uint32_t Pb = sb + SM_P;
        const uint32_t Bb = sb + SM_B0 + (uint32_t)buf * 73728;
#pragma unroll
        for (int k16 = 0; k16 < 4; k16++) {
            uint32_t af[2][4];
#pragma unroll
            for (int mt = 0; mt < 2; mt++)
                LDSM4(af[mt], Pb + (arow + mt * 16) * 144 + k16 * 32 + acolb);
            if (nidx == 0) {
                MMA16816(zac[0], af[0], ONES, ONES);
                MMA16816(zac[1], af[1], ONES, ONES);
            }
#pragma unroll
            for (int pr2 = 0; pr2 < 4; pr2++) {
                uint32_t rb = brow0 + pr2 * 16;
                uint32_t bh[4], bl[4];
                LDSM4(bh, Bb + rb * 144 + k16 * 32 + bcolb);
                LDSM4(bl, Bb + (256 + rb) * 144 + k16 * 32 + bcolb);
#pragma unroll
                for (int mt = 0; mt < 2; mt++) {
                    MMA16816(acc[mt][2 * pr2], af[mt], bh[0], bh[1]);
                    MMA16816(acc[mt][2 * pr2], af[mt], bl[0], bl[1]);
                    MMA16816(acc[mt][2 * pr2 + 1], af[mt], bh[2], bh[3]);
                    MMA16816(acc[mt][2 * pr2 + 1], af[mt], bl[2], bl[3]);
                }
            }
        }
        __syncthreads();
    }

    // ---- Z to smem ----
    float* zs = reinterpret_cast<float*>(smem + SM_ZS);
    if (nidx == 0 && (lane & 3) == 0) {
#pragma unroll
        for (int mt = 0; mt < 2; mt++) {
            int lr = midx * 32 + mt * 16 + (lane >> 2);
            zs[lr] = zac[mt][0];
            zs[lr + 8] = zac[mt][2];
        }
    }
    __syncthreads();

    // ---- epilogue: 1/Z + ELU + store ----
#pragma unroll
    for (int mt = 0; mt < 2; mt++) {
        int lr0 = midx * 32 + mt * 16 + (lane >> 2);
        float inv0 = 1.0f / zs[lr0];
        float inv1 = 1.0f / zs[lr0 + 8];
        float* o0 = out + (size_t)(i0 + lr0) * FF;
#pragma unroll
        for (int nt = 0; nt < 8; nt++) {
            int col = nidx * 64 + nt * 8 + (lane & 3) * 2;
            float v0 = acc[mt][nt][0] * inv0, v1 = acc[mt][nt][1] * inv0;
            float v2 = acc[mt][nt][2] * inv1, v3 = acc[mt][nt][3] * inv1;
            v0 = v0 > 0.f ? v0 : (__expf(v0) - 1.f);
            v1 = v1 > 0.f ? v1 : (__expf(v1) - 1.f);
            v2 = v2 > 0.f ? v2 : (__expf(v2) - 1.f);
            v3 = v3 > 0.f ? v3 : (__expf(v3) - 1.f);
            *reinterpret_cast<float2*>(o0 + col) = make_float2(v0, v1);
            *reinterpret_cast<float2*>(o0 + 8 * FF + col) = make_float2(v2, v3);
        }
    }
}

// ---------------------------------------------------------------------------
extern "C" void kernel_launch(void* const* d_in, const int* in_sizes, int n_in,
                              void* d_out, int out_size) {
    const float* X = (const float*)d_in[0];   // [8192, 512]
    const int* adj = (const int*)d_in[1];     // [8192, 8192]
    const float* W = (const float*)d_in[2];   // [512, 256]
    const float* a = (const float*)d_in[3];   // [512, 1]
    float* out = (float*)d_out;               // [8192, 256]

    cudaFuncSetAttribute(gat_hmma, cudaFuncAttributeMaxDynamicSharedMemorySize, GAT_SMEM);

    adjconv<<<(size_t)NN * NN / 2048, 256>>>(adj);
    gemm_xw<<<NN / 32, 256>>>(X, W);
    svec_kernel<<<NN / 8, 256>>>(a);
    rowm_kernel<<<1, 256>>>();
    gat_hmma<<<NN / MB, 256, GAT_SMEM>>>(out);
}

// round 8
// speedup vs baseline: 6.5605x; 1.6676x over previous
#include <cuda_runtime.h>
#include <cuda_fp16.h>
#include <cstdint>

#define NN 8192
#define FIN 512
#define FF 256
#define MB 64          // rows per CTA in gat kernel
#define KC 64          // K chunk

// ---------------- device scratch (allocation-free rule) ----------------
__device__ float  g_h[NN * FF];                  // fp32 h row-major
__device__ __half g_hT[(size_t)FF * NN];         // fp16 h, feature-major (B operand)
__device__ float  g_s1[NN], g_s2[NN];
__device__ float  g_mx;                          // global max of s2
__device__ uint32_t g_a2[NN], g_c2[NN];          // A_i,A_i / C_i,C_i packed half2
__device__ uint4  g_bd4[NN / 4];                 // (Bpair, Dpair) interleaved

// ---------------- helpers ----------------
__device__ __forceinline__ uint32_t smem_u32(const void* p) {
    uint32_t a;
    asm("{ .reg .u64 t; cvta.to.shared.u64 t, %1; cvt.u32.u64 %0, t; }" : "=r"(a) : "l"(p));
    return a;
}
__device__ __forceinline__ __half2 u2h2(uint32_t u) {
    __half2 h; *reinterpret_cast<uint32_t*>(&h) = u; return h;
}
__device__ __forceinline__ uint32_t h22u(__half2 h) {
    return *reinterpret_cast<uint32_t*>(&h);
}
#define CP16(dst, src) \
    asm volatile("cp.async.cg.shared.global [%0], [%1], 16;" :: "r"(dst), "l"(src) : "memory")
#define LDSM4(r, addr) \
    asm volatile("ldmatrix.sync.aligned.m8n8.x4.shared.b16 {%0,%1,%2,%3}, [%4];" \
        : "=r"((r)[0]), "=r"((r)[1]), "=r"((r)[2]), "=r"((r)[3]) : "r"(addr))
#define MMA16816(d, a, b0, b1) \
    asm volatile("mma.sync.aligned.m16n8k16.row.col.f32.f16.f16.f32 " \
        "{%0,%1,%2,%3},{%4,%5,%6,%7},{%8,%9},{%0,%1,%2,%3};" \
        : "+f"((d)[0]), "+f"((d)[1]), "+f"((d)[2]), "+f"((d)[3]) \
        : "r"((a)[0]), "r"((a)[1]), "r"((a)[2]), "r"((a)[3]), "r"(b0), "r"(b1))

// ---------------- SMEM layout for gat_hmma (dynamic) ----------------
#define SM_BD 0                      // 32768 B : BD tables (8192 j x 4B)
#define SM_P 32768                   // 2 x 9216 B : P tile 64 rows x 144B pitch
#define SM_B 51200                   // 2 x 36864 B : B tile 256 rows x 144B pitch
#define SM_ZS 124928                 // 256 B : Z per row
#define GAT_SMEM 125184

// ---------------------------------------------------------------------------
// Kernel 1: h = X @ W ; writes g_h (fp32) and g_hT (fp16 rn, feature-major).
// ---------------------------------------------------------------------------
__global__ __launch_bounds__(256) void gemm_xw(const float* __restrict__ X,
                                               const float* __restrict__ W) {
    __shared__ float Xs[32 * 36];
    __shared__ float T[256 * 33];
    const int t = threadIdx.x;
    const int i0 = blockIdx.x * 32;
    const int c = t;

    float acc[32];
#pragma unroll
    for (int r = 0; r < 32; r++) acc[r] = 0.f;
    const int kk = t & 31;
    const int rb = t >> 5;

    for (int k0 = 0; k0 < FIN; k0 += 32) {
#pragma unroll
        for (int q = 0; q < 4; q++) {
            int r = rb + 8 * q;
            Xs[kk * 36 + r] = X[(i0 + r) * FIN + k0 + kk];
        }
        __syncthreads();
#pragma unroll
        for (int k = 0; k < 32; k++) {
            float wv = W[(k0 + k) * FF + c];
            const float4* xp = reinterpret_cast<const float4*>(&Xs[k * 36]);
#pragma unroll
            for (int u = 0; u < 8; u++) {
                float4 xv = xp[u];
                acc[4 * u + 0] = fmaf(xv.x, wv, acc[4 * u + 0]);
                acc[4 * u + 1] = fmaf(xv.y, wv, acc[4 * u + 1]);
                acc[4 * u + 2] = fmaf(xv.z, wv, acc[4 * u + 2]);
                acc[4 * u + 3] = fmaf(xv.w, wv, acc[4 * u + 3]);
            }
        }
        __syncthreads();
    }
#pragma unroll
    for (int r = 0; r < 32; r++) {
        g_h[(i0 + r) * FF + c] = acc[r];
        T[c * 33 + r] = acc[r];
    }
    __syncthreads();
    const int warp = t >> 5, lane = t & 31;
#pragma unroll 4
    for (int ff = 0; ff < 32; ff++) {
        const int f = warp * 32 + ff;
        g_hT[(size_t)f * NN + i0 + lane] = __float2half_rn(T[f * 33 + lane]);
    }
}

// ---------------------------------------------------------------------------
// Kernel 2: s1, s2 dot products (warp per row)
// ---------------------------------------------------------------------------
__global__ __launch_bounds__(256) void svec_kernel(const float* __restrict__ a) {
    __shared__ float as[2 * FF];
    const int t = threadIdx.x;
    as[t] = a[t];
    as[t + 256] = a[t + 256];
    __syncthreads();
    const int warp = t >> 5, lane = t & 31;
    const int row = blockIdx.x * 8 + warp;
    float s1 = 0.f, s2 = 0.f;
#pragma unroll
    for (int q = 0; q < 8; q++) {
        int f = lane + 32 * q;
        float v = g_h[row * FF + f];
        s1 = fmaf(v, as[f], s1);
        s2 = fmaf(v, as[FF + f], s2);
    }
#pragma unroll
    for (int o = 16; o; o >>= 1) {
        s1 += __shfl_xor_sync(0xFFFFFFFFu, s1, o);
        s2 += __shfl_xor_sync(0xFFFFFFFFu, s2, o);
    }
    if (lane == 0) { g_s1[row] = s1; g_s2[row] = s2; }
}

// ---------------------------------------------------------------------------
// Kernel 3a: global max of s2
// ---------------------------------------------------------------------------
__global__ __launch_bounds__(1024) void maxk() {
    __shared__ float red[1024];
    const int t = threadIdx.x;
    float m = -3.0e38f;
    for (int i = t; i < NN; i += 1024) m = fmaxf(m, g_s2[i]);
    red[t] = m;
    __syncthreads();
    for (int s = 512; s; s >>= 1) {
        if (t < s) red[t] = fmaxf(red[t], red[t + s]);
        __syncthreads();
    }
    if (t == 0) g_mx = red[0];
}

// ---------------------------------------------------------------------------
// Kernel 3b: tables A_i, C_i (per row) and B_j, D_j (per col), fp16 packed.
// p_ij = adj * max(A_i*B_j, C_i*D_j) = adj * exp(lrelu(s1_i+s2_j) - m_i)
// ---------------------------------------------------------------------------
__global__ __launch_bounds__(256) void tables() {
    const int gid = blockIdx.x * 256 + threadIdx.x;
    const float mx = g_mx;
    {
        float u = g_s1[gid] + mx;
        float mm = fmaxf(u, 0.2f * u);
        __half A = __float2half_rn(expf(u - mm));
        __half C = __float2half_rn(expf(0.2f * u - mm));
        g_a2[gid] = h22u(__halves2half2(A, A));
        g_c2[gid] = h22u(__halves2half2(C, C));
    }
    if (gid < NN / 2) {
        float v0 = g_s2[2 * gid] - mx, v1 = g_s2[2 * gid + 1] - mx;
        __half B0 = __float2half_rn(expf(v0)), B1 = __float2half_rn(expf(v1));
        __half D0 = __float2half_rn(expf(0.2f * v0)), D1 = __float2half_rn(expf(0.2f * v1));
        reinterpret_cast<uint2*>(g_bd4)[gid] =
            make_uint2(h22u(__halves2half2(B0, B1)), h22u(__halves2half2(D0, D1)));
    }
}

// ---------------------------------------------------------------------------
// Kernel 4: fused GAT on HMMA. 128 CTAs x (M=64, N=256), K=8192 in 64-chunks.
// adj read directly as int32, mask built inline. Single fp16 B product.
// Double-buffered P => ONE barrier per chunk.
// ---------------------------------------------------------------------------
__global__ __launch_bounds__(256, 1) void gat_hmma(const int* __restrict__ adj,
                                                   float* __restrict__ out) {
    extern __shared__ char smem[];
    const uint32_t sb = smem_u32(smem);
    const int t = threadIdx.x;
    const int lane = t & 31, wid = t >> 5;
    const int midx = wid >> 2, nidx = wid & 3;
    const int i0 = blockIdx.x * MB;

    // preload BD tables (32 KB)
    {
        const uint4* src = g_bd4;
        uint4* dst = reinterpret_cast<uint4*>(smem + SM_BD);
#pragma unroll
        for (int q = 0; q < 8; q++) dst[t + 256 * q] = src[t + 256 * q];
    }

    // P-gen role: row pr_ (0..63), segment seg (16 j's each)
    const int pr_ = t >> 2;
    const int seg = t & 3;
    const __half2 A2 = u2h2(g_a2[i0 + pr_]);
    const __half2 C2 = u2h2(g_c2[i0 + pr_]);
    const int* adjrow = adj + (size_t)(i0 + pr_) * NN + seg * 16;

    // first B tile copy (chunk 0 -> buf 0), linear layout
    {
        const __half* sH = g_hT + (size_t)t * NN;
        const uint32_t dH = sb + SM_B + (uint32_t)t * 144;
#pragma unroll
        for (int i = 0; i < 8; i++) CP16(dH + i * 16, sH + i * 8);
        asm volatile("cp.async.commit_group;" ::: "memory");
    }
    // adj regs for chunk 0 (16 ints)
    uint4 I0 = reinterpret_cast<const uint4*>(adjrow)[0];
    uint4 I1 = reinterpret_cast<const uint4*>(adjrow)[1];
    uint4 I2 = reinterpret_cast<const uint4*>(adjrow)[2];
    uint4 I3 = reinterpret_cast<const uint4*>(adjrow)[3];
    __syncthreads();  // BD tables visible

    float acc[2][8][4];
#pragma unroll
    for (int a = 0; a < 2; a++)
#pragma unroll
        for (int b = 0; b < 8; b++)
#pragma unroll
            for (int c = 0; c < 4; c++) acc[a][b][c] = 0.f;
    float zac[2][4] = {{0.f, 0.f, 0.f, 0.f}, {0.f, 0.f, 0.f, 0.f}};
    const uint32_t ONES = 0x3C003C00u;

    // ldmatrix lane geometry (validated in R7)
    const uint32_t arow = (uint32_t)(midx * 32 + ((lane >> 3) & 1) * 8 + (lane & 7));
    const uint32_t acolb = (uint32_t)((lane >> 4) * 16);
    const uint32_t brow0 = (uint32_t)(nidx * 64 + (lane >> 4) * 8 + (lane & 7));
    const uint32_t bcolb = (uint32_t)(((lane >> 3) & 1) * 16);

#pragma unroll 1
    for (int c = 0; c < 128; c++) {
        const int buf = c & 1;
        const int jc = c * KC;

        // ---- P tile gen (exp-free, inline adj mask) into P[buf] ----
        {
            const uint4* bd4s = reinterpret_cast<const uint4*>(smem + SM_BD) + (jc >> 2) + seg * 4;
            const uint32_t pst = sb + SM_P + (uint32_t)buf * 9216 + (uint32_t)pr_ * 144 + (uint32_t)seg * 32;
            uint32_t m8[8];
            m8[0] = (uint32_t)I0.x * 0x3C00u + (uint32_t)I0.y * 0x3C000000u;
            m8[1] = (uint32_t)I0.z * 0x3C00u + (uint32_t)I0.w * 0x3C000000u;
            m8[2] = (uint32_t)I1.x * 0x3C00u + (uint32_t)I1.y * 0x3C000000u;
            m8[3] = (uint32_t)I1.z * 0x3C00u + (uint32_t)I1.w * 0x3C000000u;
            m8[4] = (uint32_t)I2.x * 0x3C00u + (uint32_t)I2.y * 0x3C000000u;
            m8[5] = (uint32_t)I2.z * 0x3C00u + (uint32_t)I2.w * 0x3C000000u;
            m8[6] = (uint32_t)I3.x * 0x3C00u + (uint32_t)I3.y * 0x3C000000u;
            m8[7] = (uint32_t)I3.z * 0x3C00u + (uint32_t)I3.w * 0x3C000000u;
#pragma unroll
            for (int q = 0; q < 4; q++) {
                uint4 bd = bd4s[q];
                __half2 m0 = __hmax2(__hmul2(A2, u2h2(bd.x)), __hmul2(C2, u2h2(bd.y)));
                __half2 m1 = __hmax2(__hmul2(A2, u2h2(bd.z)), __hmul2(C2, u2h2(bd.w)));
                uint32_t p0 = h22u(__hmul2(m0, u2h2(m8[2 * q])));
                uint32_t p1 = h22u(__hmul2(m1, u2h2(m8[2 * q + 1])));
                asm volatile("st.shared.v2.b32 [%0], {%1,%2};" :: "r"(pst + q * 8), "r"(p0), "r"(p1) : "memory");
            }
        }
        asm volatile("cp.async.wait_group 0;" ::: "memory");  // B(c) landed
        __syncthreads();  // P(c) + B(c) visible to all warps

        if (c < 127) {
            // stage B(c+1) into other buffer; prefetch adj(c+1) into regs
            const __half* sH = g_hT + (size_t)t * NN + jc + KC;
            const uint32_t dH = sb + SM_B + (uint32_t)(buf ^ 1) * 36864 + (uint32_t)t * 144;
#pragma unroll
            for (int i = 0; i < 8; i++) CP16(dH + i * 16, sH + i * 8);
            asm volatile("cp.async.commit_group;" ::: "memory");
            const uint4* na = reinterpret_cast<const uint4*>(adjrow + jc + KC);
            I0 = na[0]; I1 = na[1]; I2 = na[2]; I3 = na[3];
        }

        // ---- MMA phase ----
        const uint32_t Pb = sb + SM_P + (uint32_t)buf * 9216;
        const uint32_t Bb = sb + SM_B + (uint32_t)buf * 36864;
#pragma unroll
        for (int k16 = 0; k16 < 4; k16++) {
            uint32_t af[2][4];
#pragma unroll
            for (int mt = 0; mt < 2; mt++)
                LDSM4(af[mt], Pb + (arow + mt * 16) * 144 + k16 * 32 + acolb);
            if (nidx == 0) {
                MMA16816(zac[0], af[0], ONES, ONES);
                MMA16816(zac[1], af[1], ONES, ONES);
            }
#pragma unroll
            for (int pr2 = 0; pr2 < 4; pr2++) {
                uint32_t bh[4];
                LDSM4(bh, Bb + (brow0 + pr2 * 16) * 144 + k16 * 32 + bcolb);
#pragma unroll
                for (int mt = 0; mt < 2; mt++) {
                    MMA16816(acc[mt][2 * pr2], af[mt], bh[0], bh[1]);
                    MMA16816(acc[mt][2 * pr2 + 1], af[mt], bh[2], bh[3]);
                }
            }
        }
    }
    __syncthreads();

    // ---- Z to smem ----
    float* zs = reinterpret_cast<float*>(smem + SM_ZS);
    if (nidx == 0 && (lane & 3) == 0) {
#pragma unroll
        for (int mt = 0; mt < 2; mt++) {
            int lr = midx * 32 + mt * 16 + (lane >> 2);
            zs[lr] = zac[mt][0];
            zs[lr + 8] = zac[mt][2];
        }
    }
    __syncthreads();

    // ---- epilogue: 1/Z + ELU + store ----
#pragma unroll
    for (int mt = 0; mt < 2; mt++) {
        int lr0 = midx * 32 + mt * 16 + (lane >> 2);
        float inv0 = 1.0f / zs[lr0];
        float inv1 = 1.0f / zs[lr0 + 8];
        float* o0 = out + (size_t)(i0 + lr0) * FF;
#pragma unroll
        for (int nt = 0; nt < 8; nt++) {
            int col = nidx * 64 + nt * 8 + (lane & 3) * 2;
            float v0 = acc[mt][nt][0] * inv0, v1 = acc[mt][nt][1] * inv0;
            float v2 = acc[mt][nt][2] * inv1, v3 = acc[mt][nt][3] * inv1;
            v0 = v0 > 0.f ? v0 : (__expf(v0) - 1.f);
            v1 = v1 > 0.f ? v1 : (__expf(v1) - 1.f);
            v2 = v2 > 0.f ? v2 : (__expf(v2) - 1.f);
            v3 = v3 > 0.f ? v3 : (__expf(v3) - 1.f);
            *reinterpret_cast<float2*>(o0 + col) = make_float2(v0, v1);
            *reinterpret_cast<float2*>(o0 + 8 * FF + col) = make_float2(v2, v3);
        }
    }
}

// ---------------------------------------------------------------------------
extern "C" void kernel_launch(void* const* d_in, const int* in_sizes, int n_in,
                              void* d_out, int out_size) {
    const float* X = (const float*)d_in[0];   // [8192, 512]
    const int* adj = (const int*)d_in[1];     // [8192, 8192]
    const float* W = (const float*)d_in[2];   // [512, 256]
    const float* a = (const float*)d_in[3];   // [512, 1]
    float* out = (float*)d_out;               // [8192, 256]

    cudaFuncSetAttribute(gat_hmma, cudaFuncAttributeMaxDynamicSharedMemorySize, GAT_SMEM);

    gemm_xw<<<NN / 32, 256>>>(X, W);
    svec_kernel<<<NN / 8, 256>>>(a);
    maxk<<<1, 1024>>>();
    tables<<<NN / 256, 256>>>();
    gat_hmma<<<NN / MB, 256, GAT_SMEM>>>(adj, out);
}

// round 10
// speedup vs baseline: 7.8030x; 1.1894x over previous
#include <cuda_runtime.h>
#include <cuda_fp16.h>
#include <cstdint>

#define NN 8192
#define FIN 512
#define FF 256
#define MB 64          // rows per CTA in gat kernel
#define KC 64          // K chunk

// ---------------- device scratch (allocation-free rule) ----------------
__device__ float  g_h[NN * FF];                  // fp32 h row-major
__device__ __half g_hT[(size_t)FF * NN];         // fp16 h, feature-major (B operand)
__device__ __half g_wt_hi[(size_t)FF * FIN];     // W^T hi fp16 [n][k]
__device__ __half g_wt_lo[(size_t)FF * FIN];     // W^T lo residual
__device__ float  g_s1[NN], g_s2[NN];
__device__ float  g_mx;                          // global max of s2
__device__ uint32_t g_a2[NN], g_c2[NN];          // A_i,A_i / C_i,C_i packed half2
__device__ uint4  g_bd4[NN / 4];                 // (Bpair, Dpair) interleaved

// ---------------- helpers ----------------
__device__ __forceinline__ uint32_t smem_u32(const void* p) {
    uint32_t a;
    asm("{ .reg .u64 t; cvta.to.shared.u64 t, %1; cvt.u32.u64 %0, t; }" : "=r"(a) : "l"(p));
    return a;
}
__device__ __forceinline__ __half2 u2h2(uint32_t u) {
    __half2 h; *reinterpret_cast<uint32_t*>(&h) = u; return h;
}
__device__ __forceinline__ uint32_t h22u(__half2 h) {
    return *reinterpret_cast<uint32_t*>(&h);
}
#define CP16(dst, src) \
    asm volatile("cp.async.cg.shared.global [%0], [%1], 16;" :: "r"(dst), "l"(src) : "memory")
#define LDSM4(r, addr) \
    asm volatile("ldmatrix.sync.aligned.m8n8.x4.shared.b16 {%0,%1,%2,%3}, [%4];" \
        : "=r"((r)[0]), "=r"((r)[1]), "=r"((r)[2]), "=r"((r)[3]) : "r"(addr))
#define MMA16816(d, a, b0, b1) \
    asm volatile("mma.sync.aligned.m16n8k16.row.col.f32.f16.f16.f32 " \
        "{%0,%1,%2,%3},{%4,%5,%6,%7},{%8,%9},{%0,%1,%2,%3};" \
        : "+f"((d)[0]), "+f"((d)[1]), "+f"((d)[2]), "+f"((d)[3]) \
        : "r"((a)[0]), "r"((a)[1]), "r"((a)[2]), "r"((a)[3]), "r"(b0), "r"(b1))
#define STSV2(addr, v0, v1) \
    asm volatile("st.shared.v2.b32 [%0], {%1,%2};" :: "r"(addr), "r"(v0), "r"(v1) : "memory")

// ---------------- SMEM layouts ----------------
// gat_hmma
#define SM_BD 0                      // 32768 B : BD tables (8192 j x 4B)
#define SM_P 32768                   // 2 x 9216 B : P tile 64 rows x 144B pitch
#define SM_B 51200                   // 2 x 36864 B : B tile 256 rows x 144B pitch
#define SM_ZS 124928                 // 256 B : Z per row
#define GAT_SMEM 125184
// gemm_hmma
#define GM_AH 0                      // 9216 : A hi 64 x 144B
#define GM_AL 9216                   // 9216 : A lo
#define GM_BH 18432                  // 36864 : B hi 256 x 144B (reused as T in epilogue)
#define GM_BL 55296                  // 36864 : B lo
#define GEMM_SMEM 92160

// ---------------------------------------------------------------------------
// Kernel 0: W [512,256] fp32 -> W^T hi/lo fp16 [256,512]
// ---------------------------------------------------------------------------
__global__ __launch_bounds__(FIN) void wconv(const float* __restrict__ W) {
    const int n = blockIdx.x, k = threadIdx.x;
    float v = W[k * FF + n];
    __half h = __float2half_rn(v);
    g_wt_hi[(size_t)n * FIN + k] = h;
    g_wt_lo[(size_t)n * FIN + k] = __float2half_rn(v - __half2float(h));
}

// ---------------------------------------------------------------------------
// Kernel 1: h = X @ W on HMMA, 3-product hi/lo split (exact to ~2^-22).
// 128 CTAs x (M=64, N=256), K=512 in 8 chunks of 64.
// Epilogue writes g_h (fp32) and g_hT (fp16, feature-major) via smem transpose.
// ---------------------------------------------------------------------------
__global__ __launch_bounds__(256, 1) void gemm_hmma(const float* __restrict__ X) {
    extern __shared__ char smem[];
    const uint32_t sb = smem_u32(smem);
    const int t = threadIdx.x;
    const int lane = t & 31, wid = t >> 5;
    const int midx = wid >> 2, nidx = wid & 3;
    const int i0 = blockIdx.x * 64;

    // X prefetch role: row xr (0..63), segment xs (16 floats each)
    const int xr = t >> 2, xs = t & 3;
    const float* xptr = X + (size_t)(i0 + xr) * FIN + xs * 16;
    float4 xv[4];
#pragma unroll
    for (int q = 0; q < 4; q++) xv[q] = reinterpret_cast<const float4*>(xptr)[q];

    // B(0): Wt rows (n = t), chunk 0
    const __half* wh = g_wt_hi + (size_t)t * FIN;
    const __half* wl = g_wt_lo + (size_t)t * FIN;
    const uint32_t dBH = sb + GM_BH + (uint32_t)t * 144;
    const uint32_t dBL = sb + GM_BL + (uint32_t)t * 144;
#pragma unroll
    for (int m = 0; m < 8; m++) { CP16(dBH + m * 16, wh + m * 8); CP16(dBL + m * 16, wl + m * 8); }
    asm volatile("cp.async.commit_group;" ::: "memory");

    float acc[2][8][4];
#pragma unroll
    for (int a = 0; a < 2; a++)
#pragma unroll
        for (int b = 0; b < 8; b++)
#pragma unroll
            for (int c = 0; c < 4; c++) acc[a][b][c] = 0.f;

    const uint32_t arow = (uint32_t)(midx * 32 + ((lane >> 3) & 1) * 8 + (lane & 7));
    const uint32_t acolb = (uint32_t)((lane >> 4) * 16);
    const uint32_t brow0 = (uint32_t)(nidx * 64 + (lane >> 4) * 8 + (lane & 7));
    const uint32_t bcolb = (uint32_t)(((lane >> 3) & 1) * 16);

#pragma unroll 1
    for (int c = 0; c < 8; c++) {
        // convert + STS A(c) from regs (prev MMA readers done via trailing sync)
        {
            const uint32_t aH = sb + GM_AH + (uint32_t)xr * 144 + (uint32_t)xs * 32;
            const uint32_t aL = sb + GM_AL + (uint32_t)xr * 144 + (uint32_t)xs * 32;
#pragma unroll
            for (int q = 0; q < 4; q++) {
                float4 v = xv[q];
                __half hx = __float2half_rn(v.x), hy = __float2half_rn(v.y);
                __half hz = __float2half_rn(v.z), hw = __float2half_rn(v.w);
                __half lx = __float2half_rn(v.x - __half2float(hx));
                __half ly = __float2half_rn(v.y - __half2float(hy));
                __half lz = __float2half_rn(v.z - __half2float(hz));
                __half lw = __float2half_rn(v.w - __half2float(hw));
                STSV2(aH + q * 8, h22u(__halves2half2(hx, hy)), h22u(__halves2half2(hz, hw)));
                STSV2(aL + q * 8, h22u(__halves2half2(lx, ly)), h22u(__halves2half2(lz, lw)));
            }
        }
        asm volatile("cp.async.wait_group 0;" ::: "memory");
        __syncthreads();  // A(c), B(c) visible
        if (c < 7) {      // prefetch X chunk c+1 (hidden under MMA)
            const float* xp = xptr + (c + 1) * KC;
#pragma unroll
            for (int q = 0; q < 4; q++) xv[q] = reinterpret_cast<const float4*>(xp)[q];
        }
        // MMA: 3 products (ah*bh + al*bh + ah*bl)
#pragma unroll
        for (int k16 = 0; k16 < 4; k16++) {
            uint32_t ah[2][4], al[2][4];
#pragma unroll
            for (int mt = 0; mt < 2; mt++) {
                LDSM4(ah[mt], sb + GM_AH + (arow + mt * 16) * 144 + k16 * 32 + acolb);
                LDSM4(al[mt], sb + GM_AL + (arow + mt * 16) * 144 + k16 * 32 + acolb);
            }
#pragma unroll
            for (int pr2 = 0; pr2 < 4; pr2++) {
                uint32_t bh[4], bl[4];
                LDSM4(bh, sb + GM_BH + (brow0 + pr2 * 16) * 144 + k16 * 32 + bcolb);
                LDSM4(bl, sb + GM_BL + (brow0 + pr2 * 16) * 144 + k16 * 32 + bcolb);
#pragma unroll
                for (int mt = 0; mt < 2; mt++) {
                    MMA16816(acc[mt][2 * pr2], ah[mt], bh[0], bh[1]);
                    MMA16816(acc[mt][2 * pr2], al[mt], bh[0], bh[1]);
                    MMA16816(acc[mt][2 * pr2], ah[mt], bl[0], bl[1]);
                    MMA16816(acc[mt][2 * pr2 + 1], ah[mt], bh[2], bh[3]);
                    MMA16816(acc[mt][2 * pr2 + 1], al[mt], bh[2], bh[3]);
                    MMA16816(acc[mt][2 * pr2 + 1], ah[mt], bl[2], bl[3]);
                }
            }
        }
        __syncthreads();  // all reads of A,B done
        if (c < 7) {      // stage B(c+1)
#pragma unroll
            for (int m = 0; m < 8; m++) {
                CP16(dBH + m * 16, wh + (c + 1) * KC + m * 8);
                CP16(dBL + m * 16, wl + (c + 1) * KC + m * 8);
            }
            asm volatile("cp.async.commit_group;" ::: "memory");
        }
    }

    // ---- epilogue: g_h fp32 + transpose to g_hT fp16 ----
#pragma unroll
    for (int mt = 0; mt < 2; mt++) {
        int lr0 = midx * 32 + mt * 16 + (lane >> 2);
        float* o0 = g_h + (size_t)(i0 + lr0) * FF;
#pragma unroll
        for (int nt = 0; nt < 8; nt++) {
            int col = nidx * 64 + nt * 8 + (lane & 3) * 2;
            *reinterpret_cast<float2*>(o0 + col) = make_float2(acc[mt][nt][0], acc[mt][nt][1]);
            *reinterpret_cast<float2*>(o0 + 8 * FF + col) = make_float2(acc[mt][nt][2], acc[mt][nt][3]);
            // T in GM_BH region: T[col][row], pitch 144 B (72 halves)
            uint32_t tb = sb + GM_BH + (uint32_t)col * 144;
            *reinterpret_cast<__half*>(smem + (tb - sb) + lr0 * 2) = __float2half_rn(acc[mt][nt][0]);
            *reinterpret_cast<__half*>(smem + (tb - sb) + 144 + lr0 * 2) = __float2half_rn(acc[mt][nt][1]);
            *reinterpret_cast<__half*>(smem + (tb - sb) + (lr0 + 8) * 2) = __float2half_rn(acc[mt][nt][2]);
            *reinterpret_cast<__half*>(smem + (tb - sb) + 144 + (lr0 + 8) * 2) = __float2half_rn(acc[mt][nt][3]);
        }
    }
    __syncthreads();
    // thread f = t writes g_hT row f (64 halves = 128 B)
    {
        uint4* dst = reinterpret_cast<uint4*>(g_hT + (size_t)t * NN + i0);
#pragma unroll
        for (int i = 0; i < 8; i++)
            dst[i] = *reinterpret_cast<const uint4*>(smem + GM_BH + t * 144 + i * 16);
    }
}

// ---------------------------------------------------------------------------
// Kernel 2: s1, s2 dot products (warp per row)
// ---------------------------------------------------------------------------
__global__ __launch_bounds__(256) void svec_kernel(const float* __restrict__ a) {
    __shared__ float as[2 * FF];
    const int t = threadIdx.x;
    as[t] = a[t];
    as[t + 256] = a[t + 256];
    __syncthreads();
    const int warp = t >> 5, lane = t & 31;
    const int row = blockIdx.x * 8 + warp;
    float s1 = 0.f, s2 = 0.f;
#pragma unroll
    for (int q = 0; q < 8; q++) {
        int f = lane + 32 * q;
        float v = g_h[row * FF + f];
        s1 = fmaf(v, as[f], s1);
        s2 = fmaf(v, as[FF + f], s2);
    }
#pragma unroll
    for (int o = 16; o; o >>= 1) {
        s1 += __shfl_xor_sync(0xFFFFFFFFu, s1, o);
        s2 += __shfl_xor_sync(0xFFFFFFFFu, s2, o);
    }
    if (lane == 0) { g_s1[row] = s1; g_s2[row] = s2; }
}

// ---------------------------------------------------------------------------
// Kernel 3a: global max of s2
// ---------------------------------------------------------------------------
__global__ __launch_bounds__(1024) void maxk() {
    __shared__ float red[1024];
    const int t = threadIdx.x;
    float m = -3.0e38f;
    for (int i = t; i < NN; i += 1024) m = fmaxf(m, g_s2[i]);
    red[t] = m;
    __syncthreads();
    for (int s = 512; s; s >>= 1) {
        if (t < s) red[t] = fmaxf(red[t], red[t + s]);
        __syncthreads();
    }
    if (t == 0) g_mx = red[0];
}

// ---------------------------------------------------------------------------
// Kernel 3b: tables A_i, C_i (per row) and B_j, D_j (per col), fp16 packed.
// p_ij = adj * max(A_i*B_j, C_i*D_j) = adj * exp(lrelu(s1_i+s2_j) - m_i)
// ---------------------------------------------------------------------------
__global__ __launch_bounds__(256) void tables() {
    const int gid = blockIdx.x * 256 + threadIdx.x;
    const float mx = g_mx;
    {
        float u = g_s1[gid] + mx;
        float mm = fmaxf(u, 0.2f * u);
        __half A = __float2half_rn(expf(u - mm));
        __half C = __float2half_rn(expf(0.2f * u - mm));
        g_a2[gid] = h22u(__halves2half2(A, A));
        g_c2[gid] = h22u(__halves2half2(C, C));
    }
    if (gid < NN / 2) {
        float v0 = g_s2[2 * gid] - mx, v1 = g_s2[2 * gid + 1] - mx;
        __half B0 = __float2half_rn(expf(v0)), B1 = __float2half_rn(expf(v1));
        __half D0 = __float2half_rn(expf(0.2f * v0)), D1 = __float2half_rn(expf(0.2f * v1));
        reinterpret_cast<uint2*>(g_bd4)[gid] =
            make_uint2(h22u(__halves2half2(B0, B1)), h22u(__halves2half2(D0, D1)));
    }
}

// ---------------------------------------------------------------------------
// P tile generator (exp-free, inline adj mask) -> P buffer bufp
// ---------------------------------------------------------------------------
__device__ __forceinline__ void pgen(uint32_t sb, const char* smem, int bufp, int jc,
                                     const uint4& I0, const uint4& I1,
                                     const uint4& I2, const uint4& I3,
                                     __half2 A2, __half2 C2, int pr_, int seg) {
    const uint4* bd4s = reinterpret_cast<const uint4*>(smem + SM_BD) + (jc >> 2) + seg * 4;
    const uint32_t pst = sb + SM_P + (uint32_t)bufp * 9216 + (uint32_t)pr_ * 144 + (uint32_t)seg * 32;
    uint32_t m8[8];
    m8[0] = (uint32_t)I0.x * 0x3C00u + (uint32_t)I0.y * 0x3C000000u;
    m8[1] = (uint32_t)I0.z * 0x3C00u + (uint32_t)I0.w * 0x3C000000u;
    m8[2] = (uint32_t)I1.x * 0x3C00u + (uint32_t)I1.y * 0x3C000000u;
    m8[3] = (uint32_t)I1.z * 0x3C00u + (uint32_t)I1.w * 0x3C000000u;
    m8[4] = (uint32_t)I2.x * 0x3C00u + (uint32_t)I2.y * 0x3C000000u;
    m8[5] = (uint32_t)I2.z * 0x3C00u + (uint32_t)I2.w * 0x3C000000u;
    m8[6] = (uint32_t)I3.x * 0x3C00u + (uint32_t)I3.y * 0x3C000000u;
    m8[7] = (uint32_t)I3.z * 0x3C00u + (uint32_t)I3.w * 0x3C000000u;
#pragma unroll
    for (int q = 0; q < 4; q++) {
        uint4 bd = bd4s[q];
        __half2 m0 = __hmax2(__hmul2(A2, u2h2(bd.x)), __hmul2(C2, u2h2(bd.y)));
        __half2 m1 = __hmax2(__hmul2(A2, u2h2(bd.z)), __hmul2(C2, u2h2(bd.w)));
        uint32_t p0 = h22u(__hmul2(m0, u2h2(m8[2 * q])));
        uint32_t p1 = h22u(__hmul2(m1, u2h2(m8[2 * q + 1])));
        STSV2(pst + q * 8, p0, p1);
    }
}

// ---------------------------------------------------------------------------
// Kernel 4: fused GAT on HMMA. 128 CTAs x (M=64, N=256), K=8192 in 64-chunks.
// P-gen(c+1) interleaved INTO the MMA(c) phase (fills tensor-stall cycles).
// One barrier per chunk.
// ---------------------------------------------------------------------------
__global__ __launch_bounds__(256, 1) void gat_hmma(const int* __restrict__ adj,
                                                   float* __restrict__ out) {
    extern __shared__ char smem[];
    const uint32_t sb = smem_u32(smem);
    const int t = threadIdx.x;
    const int lane = t & 31, wid = t >> 5;
    const int midx = wid >> 2, nidx = wid & 3;
    const int i0 = blockIdx.x * MB;

    // preload BD tables (32 KB)
    {
        const uint4* src = g_bd4;
        uint4* dst = reinterpret_cast<uint4*>(smem + SM_BD);
#pragma unroll
        for (int q = 0; q < 8; q++) dst[t + 256 * q] = src[t + 256 * q];
    }

    const int pr_ = t >> 2;
    const int seg = t & 3;
    const __half2 A2 = u2h2(g_a2[i0 + pr_]);
    const __half2 C2 = u2h2(g_c2[i0 + pr_]);
    const int* adjrow = adj + (size_t)(i0 + pr_) * NN + seg * 16;

    // B(0) cp.async (linear layout)
    {
        const __half* sH = g_hT + (size_t)t * NN;
        const uint32_t dH = sb + SM_B + (uint32_t)t * 144;
#pragma unroll
        for (int i = 0; i < 8; i++) CP16(dH + i * 16, sH + i * 8);
        asm volatile("cp.async.commit_group;" ::: "memory");
    }
    // adj chunk 0
    uint4 I0 = reinterpret_cast<const uint4*>(adjrow)[0];
    uint4 I1 = reinterpret_cast<const uint4*>(adjrow)[1];
    uint4 I2 = reinterpret_cast<const uint4*>(adjrow)[2];
    uint4 I3 = reinterpret_cast<const uint4*>(adjrow)[3];
    __syncthreads();  // BD visible
    pgen(sb, smem, 0, 0, I0, I1, I2, I3, A2, C2, pr_, seg);  // P(0)
    {   // adj chunk 1
        const uint4* na = reinterpret_cast<const uint4*>(adjrow + KC);
        I0 = na[0]; I1 = na[1]; I2 = na[2]; I3 = na[3];
    }

    float acc[2][8][4];
#pragma unroll
    for (int a = 0; a < 2; a++)
#pragma unroll
        for (int b = 0; b < 8; b++)
#pragma unroll
            for (int c = 0; c < 4; c++) acc[a][b][c] = 0.f;
    float zac[2][4] = {{0.f, 0.f, 0.f, 0.f}, {0.f, 0.f, 0.f, 0.f}};
    const uint32_t ONES = 0x3C003C00u;

    const uint32_t arow = (uint32_t)(midx * 32 + ((lane >> 3) & 1) * 8 + (lane & 7));
    const uint32_t acolb = (uint32_t)((lane >> 4) * 16);
    const uint32_t brow0 = (uint32_t)(nidx * 64 + (lane >> 4) * 8 + (lane & 7));
    const uint32_t bcolb = (uint32_t)(((lane >> 3) & 1) * 16);

#pragma unroll 1
    for (int c = 0; c < 128; c++) {
        const int buf = c & 1;
        const int jc = c * KC;

        asm volatile("cp.async.wait_group 0;" ::: "memory");  // B(c) landed
        __syncthreads();                                      // P(c) + B(c) visible

        if (c < 127) {  // stage B(c+1)
            const __half* sH = g_hT + (size_t)t * NN + jc + KC;
            const uint32_t dH = sb + SM_B + (uint32_t)(buf ^ 1) * 36864 + (uint32_t)t * 144;
#pragma unroll
            for (int i = 0; i < 8; i++) CP16(dH + i * 16, sH + i * 8);
            asm volatile("cp.async.commit_group;" ::: "memory");
        }

        const uint32_t Pb = sb + SM_P + (uint32_t)buf * 9216;
        const uint32_t Bb = sb + SM_B + (uint32_t)buf * 36864;

        // ---- MMA k16 = 0,1 ----
#pragma unroll
        for (int k16 = 0; k16 < 2; k16++) {
            uint32_t af[2][4];
#pragma unroll
            for (int mt = 0; mt < 2; mt++)
                LDSM4(af[mt], Pb + (arow + mt * 16) * 144 + k16 * 32 + acolb);
            if (nidx == 0) {
                MMA16816(zac[0], af[0], ONES, ONES);
                MMA16816(zac[1], af[1], ONES, ONES);
            }
#pragma unroll
            for (int pr2 = 0; pr2 < 4; pr2++) {
                uint32_t bh[4];
                LDSM4(bh, Bb + (brow0 + pr2 * 16) * 144 + k16 * 32 + bcolb);
#pragma unroll
                for (int mt = 0; mt < 2; mt++) {
                    MMA16816(acc[mt][2 * pr2], af[mt], bh[0], bh[1]);
                    MMA16816(acc[mt][2 * pr2 + 1], af[mt], bh[2], bh[3]);
                }
            }
        }

        // ---- P-gen(c+1) into other buffer (no barrier needed: disjoint) ----
        if (c < 127)
            pgen(sb, smem, buf ^ 1, jc + KC, I0, I1, I2, I3, A2, C2, pr_, seg);
        if (c < 126) {  // adj chunk c+2
            const uint4* na = reinterpret_cast<const uint4*>(adjrow + jc + 2 * KC);
            I0 = na[0]; I1 = na[1]; I2 = na[2]; I3 = na[3];
        }

        // ---- MMA k16 = 2,3 ----
#pragma unroll
        for (int k16 = 2; k16 < 4; k16++) {
            uint32_t af[2][4];
#pragma unroll
            for (int mt = 0; mt < 2; mt++)
                LDSM4(af[mt], Pb + (arow + mt * 16) * 144 + k16 * 32 + acolb);
            if (nidx == 0) {
                MMA16816(zac[0], af[0], ONES, ONES);
                MMA16816(zac[1], af[1], ONES, ONES);
            }
#pragma unroll
            for (int pr2 = 0; pr2 < 4; pr2++) {
                uint32_t bh[4];
                LDSM4(bh, Bb + (brow0 + pr2 * 16) * 144 + k16 * 32 + bcolb);
#pragma unroll
                for (int mt = 0; mt < 2; mt++) {
                    MMA16816(acc[mt][2 * pr2], af[mt], bh[0], bh[1]);
                    MMA16816(acc[mt][2 * pr2 + 1], af[mt], bh[2], bh[3]);
                }
            }
        }
    }
    __syncthreads();

    // ---- Z to smem ----
    float* zs = reinterpret_cast<float*>(smem + SM_ZS);
    if (nidx == 0 && (lane & 3) == 0) {
#pragma unroll
        for (int mt = 0; mt < 2; mt++) {
            int lr = midx * 32 + mt * 16 + (lane >> 2);
            zs[lr] = zac[mt][0];
            zs[lr + 8] = zac[mt][2];
        }
    }
    __syncthreads();

    // ---- epilogue: 1/Z + ELU + store ----
#pragma unroll
    for (int mt = 0; mt < 2; mt++) {
        int lr0 = midx * 32 + mt * 16 + (lane >> 2);
        float inv0 = 1.0f / zs[lr0];
        float inv1 = 1.0f / zs[lr0 + 8];
        float* o0 = out + (size_t)(i0 + lr0) * FF;
#pragma unroll
        for (int nt = 0; nt < 8; nt++) {
            int col = nidx * 64 + nt * 8 + (lane & 3) * 2;
            float v0 = acc[mt][nt][0] * inv0, v1 = acc[mt][nt][1] * inv0;
            float v2 = acc[mt][nt][2] * inv1, v3 = acc[mt][nt][3] * inv1;
            v0 = v0 > 0.f ? v0 : (__expf(v0) - 1.f);
            v1 = v1 > 0.f ? v1 : (__expf(v1) - 1.f);
            v2 = v2 > 0.f ? v2 : (__expf(v2) - 1.f);
            v3 = v3 > 0.f ? v3 : (__expf(v3) - 1.f);
            *reinterpret_cast<float2*>(o0 + col) = make_float2(v0, v1);
            *reinterpret_cast<float2*>(o0 + 8 * FF + col) = make_float2(v2, v3);
        }
    }
}

// ---------------------------------------------------------------------------
extern "C" void kernel_launch(void* const* d_in, const int* in_sizes, int n_in,
                              void* d_out, int out_size) {
    const float* X = (const float*)d_in[0];   // [8192, 512]
    const int* adj = (const int*)d_in[1];     // [8192, 8192]
    const float* W = (const float*)d_in[2];   // [512, 256]
    const float* a = (const float*)d_in[3];   // [512, 1]
    float* out = (float*)d_out;               // [8192, 256]

    cudaFuncSetAttribute(gemm_hmma, cudaFuncAttributeMaxDynamicSharedMemorySize, GEMM_SMEM);
    cudaFuncSetAttribute(gat_hmma, cudaFuncAttributeMaxDynamicSharedMemorySize, GAT_SMEM);

    wconv<<<FF, FIN>>>(W);
    gemm_hmma<<<NN / 64, 256, GEMM_SMEM>>>(X);
    svec_kernel<<<NN / 8, 256>>>(a);
    maxk<<<1, 1024>>>();
    tables<<<NN / 256, 256>>>();
    gat_hmma<<<NN / MB, 256, GAT_SMEM>>>(adj, out);
}

// round 11
// speedup vs baseline: 8.4891x; 1.0879x over previous
#include <cuda_runtime.h>
#include <cuda_fp16.h>
#include <cstdint>

#define NN 8192
#define FIN 512
#define FF 256
#define MB 64          // rows per CTA in gat kernel
#define KC 64          // K chunk

// ---------------- device scratch (allocation-free rule) ----------------
__device__ float  g_h[NN * FF];                  // fp32 h row-major
__device__ __half g_hT[(size_t)FF * NN];         // fp16 h, feature-major (B operand)
__device__ __half g_wt_hi[(size_t)FF * FIN];     // W^T hi fp16 [n][k]
__device__ float  g_s1[NN], g_s2[NN];
__device__ unsigned g_mxkey;                     // ordered-uint key of max(s2)

// ---------------- helpers ----------------
__device__ __forceinline__ uint32_t smem_u32(const void* p) {
    uint32_t a;
    asm("{ .reg .u64 t; cvta.to.shared.u64 t, %1; cvt.u32.u64 %0, t; }" : "=r"(a) : "l"(p));
    return a;
}
__device__ __forceinline__ __half2 u2h2(uint32_t u) {
    __half2 h; *reinterpret_cast<uint32_t*>(&h) = u; return h;
}
__device__ __forceinline__ uint32_t h22u(__half2 h) {
    return *reinterpret_cast<uint32_t*>(&h);
}
__device__ __forceinline__ unsigned f2key(float f) {
    unsigned b = __float_as_uint(f);
    return (b & 0x80000000u) ? ~b : (b ^ 0x80000000u);
}
__device__ __forceinline__ float key2f(unsigned k) {
    unsigned b = (k & 0x80000000u) ? (k ^ 0x80000000u) : ~k;
    return __uint_as_float(b);
}
#define CP16(dst, src) \
    asm volatile("cp.async.cg.shared.global [%0], [%1], 16;" :: "r"(dst), "l"(src) : "memory")
#define LDSM4(r, addr) \
    asm volatile("ldmatrix.sync.aligned.m8n8.x4.shared.b16 {%0,%1,%2,%3}, [%4];" \
        : "=r"((r)[0]), "=r"((r)[1]), "=r"((r)[2]), "=r"((r)[3]) : "r"(addr))
#define MMA16816(d, a, b0, b1) \
    asm volatile("mma.sync.aligned.m16n8k16.row.col.f32.f16.f16.f32 " \
        "{%0,%1,%2,%3},{%4,%5,%6,%7},{%8,%9},{%0,%1,%2,%3};" \
        : "+f"((d)[0]), "+f"((d)[1]), "+f"((d)[2]), "+f"((d)[3]) \
        : "r"((a)[0]), "r"((a)[1]), "r"((a)[2]), "r"((a)[3]), "r"(b0), "r"(b1))
#define STSV2(addr, v0, v1) \
    asm volatile("st.shared.v2.b32 [%0], {%1,%2};" :: "r"(addr), "r"(v0), "r"(v1) : "memory")

// ---------------- SMEM layouts ----------------
// gat_hmma
#define SM_BD 0                      // 32768 B : BD tables (8192 j x 4B, uint2 per j-pair)
#define SM_P 32768                   // 2 x 9216 B : P tile 64 rows x 144B pitch
#define SM_B 51200                   // 2 x 36864 B : B tile 256 rows x 144B pitch
#define SM_AC 124928                 // 512 B : A2/C2 per row (prologue only)
#define SM_ZS 124928                 // 256 B : Z per row (epilogue; reuses AC space)
#define GAT_SMEM 125440
// gemm_hmma
#define GM_AH 0                      // 9216 : A hi 64 x 144B
#define GM_AL 9216                   // 9216 : A lo
#define GM_BH 18432                  // 36864 : B hi 256 x 144B (reused as T in epilogue)
#define GEMM_SMEM 55296

// ---------------------------------------------------------------------------
// Kernel 0: W [512,256] fp32 -> W^T hi fp16 [256,512]; also reset g_mxkey.
// ---------------------------------------------------------------------------
__global__ __launch_bounds__(FIN) void wconv(const float* __restrict__ W) {
    const int n = blockIdx.x, k = threadIdx.x;
    if (n == 0 && k == 0) g_mxkey = 0u;   // below every encoded float
    g_wt_hi[(size_t)n * FIN + k] = __float2half_rn(W[k * FF + n]);
}

// ---------------------------------------------------------------------------
// Kernel 1: h = X @ W on HMMA, 2-product split (Xh*Wh + Xl*Wh).
// 128 CTAs x (M=64, N=256), K=512 in 8 chunks of 64.
// Epilogue writes g_h (fp32) and g_hT (fp16, feature-major) via smem transpose.
// ---------------------------------------------------------------------------
__global__ __launch_bounds__(256, 1) void gemm_hmma(const float* __restrict__ X) {
    extern __shared__ char smem[];
    const uint32_t sb = smem_u32(smem);
    const int t = threadIdx.x;
    const int lane = t & 31, wid = t >> 5;
    const int midx = wid >> 2, nidx = wid & 3;
    const int i0 = blockIdx.x * 64;

    // X prefetch role: row xr (0..63), segment xs (16 floats each)
    const int xr = t >> 2, xs = t & 3;
    const float* xptr = X + (size_t)(i0 + xr) * FIN + xs * 16;
    float4 xv[4];
#pragma unroll
    for (int q = 0; q < 4; q++) xv[q] = reinterpret_cast<const float4*>(xptr)[q];

    // B(0): Wt rows (n = t), chunk 0
    const __half* wh = g_wt_hi + (size_t)t * FIN;
    const uint32_t dBH = sb + GM_BH + (uint32_t)t * 144;
#pragma unroll
    for (int m = 0; m < 8; m++) CP16(dBH + m * 16, wh + m * 8);
    asm volatile("cp.async.commit_group;" ::: "memory");

    float acc[2][8][4];
#pragma unroll
    for (int a = 0; a < 2; a++)
#pragma unroll
        for (int b = 0; b < 8; b++)
#pragma unroll
            for (int c = 0; c < 4; c++) acc[a][b][c] = 0.f;

    const uint32_t arow = (uint32_t)(midx * 32 + ((lane >> 3) & 1) * 8 + (lane & 7));
    const uint32_t acolb = (uint32_t)((lane >> 4) * 16);
    const uint32_t brow0 = (uint32_t)(nidx * 64 + (lane >> 4) * 8 + (lane & 7));
    const uint32_t bcolb = (uint32_t)(((lane >> 3) & 1) * 16);

#pragma unroll 1
    for (int c = 0; c < 8; c++) {
        // convert + STS A(c) hi/lo from regs
        {
            const uint32_t aH = sb + GM_AH + (uint32_t)xr * 144 + (uint32_t)xs * 32;
            const uint32_t aL = sb + GM_AL + (uint32_t)xr * 144 + (uint32_t)xs * 32;
#pragma unroll
            for (int q = 0; q < 4; q++) {
                float4 v = xv[q];
                __half hx = __float2half_rn(v.x), hy = __float2half_rn(v.y);
                __half hz = __float2half_rn(v.z), hw = __float2half_rn(v.w);
                __half lx = __float2half_rn(v.x - __half2float(hx));
                __half ly = __float2half_rn(v.y - __half2float(hy));
                __half lz = __float2half_rn(v.z - __half2float(hz));
                __half lw = __float2half_rn(v.w - __half2float(hw));
                STSV2(aH + q * 8, h22u(__halves2half2(hx, hy)), h22u(__halves2half2(hz, hw)));
                STSV2(aL + q * 8, h22u(__halves2half2(lx, ly)), h22u(__halves2half2(lz, lw)));
            }
        }
        asm volatile("cp.async.wait_group 0;" ::: "memory");
        __syncthreads();  // A(c), B(c) visible
        if (c < 7) {      // prefetch X chunk c+1 (hidden under MMA)
            const float* xp = xptr + (c + 1) * KC;
#pragma unroll
            for (int q = 0; q < 4; q++) xv[q] = reinterpret_cast<const float4*>(xp)[q];
        }
        // MMA: 2 products (ah*bh + al*bh)
#pragma unroll
        for (int k16 = 0; k16 < 4; k16++) {
            uint32_t ah[2][4], al[2][4];
#pragma unroll
            for (int mt = 0; mt < 2; mt++) {
                LDSM4(ah[mt], sb + GM_AH + (arow + mt * 16) * 144 + k16 * 32 + acolb);
                LDSM4(al[mt], sb + GM_AL + (arow + mt * 16) * 144 + k16 * 32 + acolb);
            }
#pragma unroll
            for (int pr2 = 0; pr2 < 4; pr2++) {
                uint32_t bh[4];
                LDSM4(bh, sb + GM_BH + (brow0 + pr2 * 16) * 144 + k16 * 32 + bcolb);
#pragma unroll
                for (int mt = 0; mt < 2; mt++) {
                    MMA16816(acc[mt][2 * pr2], ah[mt], bh[0], bh[1]);
                    MMA16816(acc[mt][2 * pr2], al[mt], bh[0], bh[1]);
                    MMA16816(acc[mt][2 * pr2 + 1], ah[mt], bh[2], bh[3]);
                    MMA16816(acc[mt][2 * pr2 + 1], al[mt], bh[2], bh[3]);
                }
            }
        }
        __syncthreads();  // all reads of A,B done
        if (c < 7) {      // stage B(c+1)
#pragma unroll
            for (int m = 0; m < 8; m++) CP16(dBH + m * 16, wh + (c + 1) * KC + m * 8);
            asm volatile("cp.async.commit_group;" ::: "memory");
        }
    }

    // ---- epilogue: g_h fp32 + transpose to g_hT fp16 ----
#pragma unroll
    for (int mt = 0; mt < 2; mt++) {
        int lr0 = midx * 32 + mt * 16 + (lane >> 2);
        float* o0 = g_h + (size_t)(i0 + lr0) * FF;
#pragma unroll
        for (int nt = 0; nt < 8; nt++) {
            int col = nidx * 64 + nt * 8 + (lane & 3) * 2;
            *reinterpret_cast<float2*>(o0 + col) = make_float2(acc[mt][nt][0], acc[mt][nt][1]);
            *reinterpret_cast<float2*>(o0 + 8 * FF + col) = make_float2(acc[mt][nt][2], acc[mt][nt][3]);
            char* tb = smem + GM_BH + col * 144;
            *reinterpret_cast<__half*>(tb + lr0 * 2) = __float2half_rn(acc[mt][nt][0]);
            *reinterpret_cast<__half*>(tb + 144 + lr0 * 2) = __float2half_rn(acc[mt][nt][1]);
            *reinterpret_cast<__half*>(tb + (lr0 + 8) * 2) = __float2half_rn(acc[mt][nt][2]);
            *reinterpret_cast<__half*>(tb + 144 + (lr0 + 8) * 2) = __float2half_rn(acc[mt][nt][3]);
        }
    }
    __syncthreads();
    {   // thread f = t writes g_hT row f (64 halves = 128 B)
        uint4* dst = reinterpret_cast<uint4*>(g_hT + (size_t)t * NN + i0);
#pragma unroll
        for (int i = 0; i < 8; i++)
            dst[i] = *reinterpret_cast<const uint4*>(smem + GM_BH + t * 144 + i * 16);
    }
}

// ---------------------------------------------------------------------------
// Kernel 2: s1, s2 dot products (warp per row) + global max(s2) via atomicMax
// ---------------------------------------------------------------------------
__global__ __launch_bounds__(256) void svec_kernel(const float* __restrict__ a) {
    __shared__ float as[2 * FF];
    const int t = threadIdx.x;
    as[t] = a[t];
    as[t + 256] = a[t + 256];
    __syncthreads();
    const int warp = t >> 5, lane = t & 31;
    const int row = blockIdx.x * 8 + warp;
    float s1 = 0.f, s2 = 0.f;
#pragma unroll
    for (int q = 0; q < 8; q++) {
        int f = lane + 32 * q;
        float v = g_h[row * FF + f];
        s1 = fmaf(v, as[f], s1);
        s2 = fmaf(v, as[FF + f], s2);
    }
#pragma unroll
    for (int o = 16; o; o >>= 1) {
        s1 += __shfl_xor_sync(0xFFFFFFFFu, s1, o);
        s2 += __shfl_xor_sync(0xFFFFFFFFu, s2, o);
    }
    if (lane == 0) {
        g_s1[row] = s1;
        g_s2[row] = s2;
        atomicMax(&g_mxkey, f2key(s2));
    }
}

// ---------------------------------------------------------------------------
// P tile generator (exp-free, inline adj mask) -> P buffer bufp; accumulates Z
// in fp32 from the SAME quantized fp16 p values that feed the MMA.
// ---------------------------------------------------------------------------
__device__ __forceinline__ void pgen(uint32_t sb, const char* smem, int bufp, int jc,
                                     const uint4& I0, const uint4& I1,
                                     const uint4& I2, const uint4& I3,
                                     __half2 A2, __half2 C2, int pr_, int seg,
                                     float& z) {
    const uint4* bd4s = reinterpret_cast<const uint4*>(smem + SM_BD) + (jc >> 2) + seg * 4;
    const uint32_t pst = sb + SM_P + (uint32_t)bufp * 9216 + (uint32_t)pr_ * 144 + (uint32_t)seg * 32;
    uint32_t m8[8];
    m8[0] = (uint32_t)I0.x * 0x3C00u + (uint32_t)I0.y * 0x3C000000u;
    m8[1] = (uint32_t)I0.z * 0x3C00u + (uint32_t)I0.w * 0x3C000000u;
    m8[2] = (uint32_t)I1.x * 0x3C00u + (uint32_t)I1.y * 0x3C000000u;
    m8[3] = (uint32_t)I1.z * 0x3C00u + (uint32_t)I1.w * 0x3C000000u;
    m8[4] = (uint32_t)I2.x * 0x3C00u + (uint32_t)I2.y * 0x3C000000u;
    m8[5] = (uint32_t)I2.z * 0x3C00u + (uint32_t)I2.w * 0x3C000000u;
    m8[6] = (uint32_t)I3.x * 0x3C00u + (uint32_t)I3.y * 0x3C000000u;
    m8[7] = (uint32_t)I3.z * 0x3C00u + (uint32_t)I3.w * 0x3C000000u;
#pragma unroll
    for (int q = 0; q < 4; q++) {
        uint4 bd = bd4s[q];
        __half2 m0 = __hmax2(__hmul2(A2, u2h2(bd.x)), __hmul2(C2, u2h2(bd.y)));
        __half2 m1 = __hmax2(__hmul2(A2, u2h2(bd.z)), __hmul2(C2, u2h2(bd.w)));
        __half2 r0 = __hmul2(m0, u2h2(m8[2 * q]));
        __half2 r1 = __hmul2(m1, u2h2(m8[2 * q + 1]));
        STSV2(pst + q * 8, h22u(r0), h22u(r1));
        float2 f0 = __half22float2(r0), f1 = __half22float2(r1);
        z += (f0.x + f0.y) + (f1.x + f1.y);
    }
}

// ---------------------------------------------------------------------------
// Kernel 4: fused GAT on HMMA. 128 CTAs x (M=64, N=256), K=8192 in 64-chunks.
// BD/AC tables built in prologue (no table kernels). No Z-MMA: Z from pgen.
// P-gen(c+1) interleaved into MMA(c); one barrier per chunk.
// ---------------------------------------------------------------------------
__global__ __launch_bounds__(256, 1) void gat_hmma(const int* __restrict__ adj,
                                                   float* __restrict__ out) {
    extern __shared__ char smem[];
    const uint32_t sb = smem_u32(smem);
    const int t = threadIdx.x;
    const int lane = t & 31, wid = t >> 5;
    const int midx = wid >> 2, nidx = wid & 3;
    const int i0 = blockIdx.x * MB;

    const int pr_ = t >> 2;
    const int seg = t & 3;
    const int* adjrow = adj + (size_t)(i0 + pr_) * NN + seg * 16;

    // B(0) cp.async early (overlaps table gen)
    {
        const __half* sH = g_hT + (size_t)t * NN;
        const uint32_t dH = sb + SM_B + (uint32_t)t * 144;
#pragma unroll
        for (int i = 0; i < 8; i++) CP16(dH + i * 16, sH + i * 8);
        asm volatile("cp.async.commit_group;" ::: "memory");
    }
    // adj chunk 0 (LDG latency overlaps table gen)
    uint4 I0 = reinterpret_cast<const uint4*>(adjrow)[0];
    uint4 I1 = reinterpret_cast<const uint4*>(adjrow)[1];
    uint4 I2 = reinterpret_cast<const uint4*>(adjrow)[2];
    uint4 I3 = reinterpret_cast<const uint4*>(adjrow)[3];

    // ---- build BD tables (8192 j) + AC (64 rows) in smem ----
    const float mx = key2f(g_mxkey);
    {
        const float2* s2p = reinterpret_cast<const float2*>(g_s2);
        uint2* bd = reinterpret_cast<uint2*>(smem + SM_BD);
        for (int j2 = t; j2 < NN / 2; j2 += 256) {
            float2 v = s2p[j2];
            float v0 = v.x - mx, v1 = v.y - mx;
            __half B0 = __float2half_rn(__expf(v0)), B1 = __float2half_rn(__expf(v1));
            __half D0 = __float2half_rn(__expf(0.2f * v0)), D1 = __float2half_rn(__expf(0.2f * v1));
            bd[j2] = make_uint2(h22u(__halves2half2(B0, B1)), h22u(__halves2half2(D0, D1)));
        }
        if (t < MB) {
            float u = g_s1[i0 + t] + mx;
            float mm = fmaxf(u, 0.2f * u);
            __half A = __float2half_rn(__expf(u - mm));
            __half C = __float2half_rn(__expf(0.2f * u - mm));
            reinterpret_cast<uint2*>(smem + SM_AC)[t] =
                make_uint2(h22u(__halves2half2(A, A)), h22u(__halves2half2(C, C)));
        }
    }
    __syncthreads();  // BD + AC visible
    const uint2 ac = reinterpret_cast<const uint2*>(smem + SM_AC)[pr_];
    const __half2 A2 = u2h2(ac.x);
    const __half2 C2 = u2h2(ac.y);

    float z = 0.f;
    pgen(sb, smem, 0, 0, I0, I1, I2, I3, A2, C2, pr_, seg, z);  // P(0)
    {   // adj chunk 1
        const uint4* na = reinterpret_cast<const uint4*>(adjrow + KC);
        I0 = na[0]; I1 = na[1]; I2 = na[2]; I3 = na[3];
    }

    float acc[2][8][4];
#pragma unroll
    for (int a = 0; a < 2; a++)
#pragma unroll
        for (int b = 0; b < 8; b++)
#pragma unroll
            for (int c = 0; c < 4; c++) acc[a][b][c] = 0.f;

    const uint32_t arow = (uint32_t)(midx * 32 + ((lane >> 3) & 1) * 8 + (lane & 7));
    const uint32_t acolb = (uint32_t)((lane >> 4) * 16);
    const uint32_t brow0 = (uint32_t)(nidx * 64 + (lane >> 4) * 8 + (lane & 7));
    const uint32_t bcolb = (uint32_t)(((lane >> 3) & 1) * 16);

#pragma unroll 1
    for (int c = 0; c < 128; c++) {
        const int buf = c & 1;
        const int jc = c * KC;

        asm volatile("cp.async.wait_group 0;" ::: "memory");  // B(c) landed
        __syncthreads();                                      // P(c) + B(c) visible

        if (c < 127) {  // stage B(c+1)
            const __half* sH = g_hT + (size_t)t * NN + jc + KC;
            const uint32_t dH = sb + SM_B + (uint32_t)(buf ^ 1) * 36864 + (uint32_t)t * 144;
#pragma unroll
            for (int i = 0; i < 8; i++) CP16(dH + i * 16, sH + i * 8);
            asm volatile("cp.async.commit_group;" ::: "memory");
        }

        const uint32_t Pb = sb + SM_P + (uint32_t)buf * 9216;
        const uint32_t Bb = sb + SM_B + (uint32_t)buf * 36864;

        // ---- MMA k16 = 0,1 ----
#pragma unroll
        for (int k16 = 0; k16 < 2; k16++) {
            uint32_t af[2][4];
#pragma unroll
            for (int mt = 0; mt < 2; mt++)
                LDSM4(af[mt], Pb + (arow + mt * 16) * 144 + k16 * 32 + acolb);
#pragma unroll
            for (int pr2 = 0; pr2 < 4; pr2++) {
                uint32_t bh[4];
                LDSM4(bh, Bb + (brow0 + pr2 * 16) * 144 + k16 * 32 + bcolb);
#pragma unroll
                for (int mt = 0; mt < 2; mt++) {
                    MMA16816(acc[mt][2 * pr2], af[mt], bh[0], bh[1]);
                    MMA16816(acc[mt][2 * pr2 + 1], af[mt], bh[2], bh[3]);
                }
            }
        }

        // ---- P-gen(c+1) into other buffer (disjoint; no barrier) ----
        if (c < 127)
            pgen(sb, smem, buf ^ 1, jc + KC, I0, I1, I2, I3, A2, C2, pr_, seg, z);
        if (c < 126) {  // adj chunk c+2
            const uint4* na = reinterpret_cast<const uint4*>(adjrow + jc + 2 * KC);
            I0 = na[0]; I1 = na[1]; I2 = na[2]; I3 = na[3];
        }

        // ---- MMA k16 = 2,3 ----
#pragma unroll
        for (int k16 = 2; k16 < 4; k16++) {
            uint32_t af[2][4];
#pragma unroll
            for (int mt = 0; mt < 2; mt++)
                LDSM4(af[mt], Pb + (arow + mt * 16) * 144 + k16 * 32 + acolb);
#pragma unroll
            for (int pr2 = 0; pr2 < 4; pr2++) {
                uint32_t bh[4];
                LDSM4(bh, Bb + (brow0 + pr2 * 16) * 144 + k16 * 32 + bcolb);
#pragma unroll
                for (int mt = 0; mt < 2; mt++) {
                    MMA16816(acc[mt][2 * pr2], af[mt], bh[0], bh[1]);
                    MMA16816(acc[mt][2 * pr2 + 1], af[mt], bh[2], bh[3]);
                }
            }
        }
    }
    __syncthreads();

    // ---- Z: reduce over the 4 seg-threads of each row (same warp quad) ----
    z += __shfl_xor_sync(0xFFFFFFFFu, z, 1);
    z += __shfl_xor_sync(0xFFFFFFFFu, z, 2);
    float* zs = reinterpret_cast<float*>(smem + SM_ZS);
    if (seg == 0) zs[pr_] = z;
    __syncthreads();

    // ---- epilogue: 1/Z + ELU + store ----
#pragma unroll
    for (int mt = 0; mt < 2; mt++) {
        int lr0 = midx * 32 + mt * 16 + (lane >> 2);
        float inv0 = 1.0f / zs[lr0];
        float inv1 = 1.0f / zs[lr0 + 8];
        float* o0 = out + (size_t)(i0 + lr0) * FF;
#pragma unroll
        for (int nt = 0; nt < 8; nt++) {
            int col = nidx * 64 + nt * 8 + (lane & 3) * 2;
            float v0 = acc[mt][nt][0] * inv0, v1 = acc[mt][nt][1] * inv0;
            float v2 = acc[mt][nt][2] * inv1, v3 = acc[mt][nt][3] * inv1;
            v0 = v0 > 0.f ? v0 : (__expf(v0) - 1.f);
            v1 = v1 > 0.f ? v1 : (__expf(v1) - 1.f);
            v2 = v2 > 0.f ? v2 : (__expf(v2) - 1.f);
            v3 = v3 > 0.f ? v3 : (__expf(v3) - 1.f);
            *reinterpret_cast<float2*>(o0 + col) = make_float2(v0, v1);
            *reinterpret_cast<float2*>(o0 + 8 * FF + col) = make_float2(v2, v3);
        }
    }
}

// ---------------------------------------------------------------------------
extern "C" void kernel_launch(void* const* d_in, const int* in_sizes, int n_in,
                              void* d_out, int out_size) {
    const float* X = (const float*)d_in[0];   // [8192, 512]
    const int* adj = (const int*)d_in[1];     // [8192, 8192]
    const float* W = (const float*)d_in[2];   // [512, 256]
    const float* a = (const float*)d_in[3];   // [512, 1]
    float* out = (float*)d_out;               // [8192, 256]

    cudaFuncSetAttribute(gemm_hmma, cudaFuncAttributeMaxDynamicSharedMemorySize, GEMM_SMEM);
    cudaFuncSetAttribute(gat_hmma, cudaFuncAttributeMaxDynamicSharedMemorySize, GAT_SMEM);

    wconv<<<FF, FIN>>>(W);
    gemm_hmma<<<NN / 64, 256, GEMM_SMEM>>>(X);
    svec_kernel<<<NN / 8, 256>>>(a);
    gat_hmma<<<NN / MB, 256, GAT_SMEM>>>(adj, out);
}